// round 15
// baseline (speedup 1.0000x reference)
#include <cuda_runtime.h>

#define NN      50000
#define NEMAX   800000
#define D       128
#define SCAN_B  512

// ---------------- scratch (static device globals; no runtime alloc) ----------
// g_count invariant: zero at entry of every kernel_launch call.
// (a) zero-init at module load; (b) k_epi re-zeroes it each call.
__device__ __align__(16) float g_v1[D];
__device__ __align__(16) float g_v2[D];
__device__ float g_C;
__device__ float g_p1[NN];
__device__ float g_p2[NN];
__device__ int   g_count[NN];
__device__ int   g_off[NN + 1];
__device__ int   g_woff[NN];
__device__ unsigned long long g_spack[NEMAX];      // {src:hi32, attn:lo32}

// packed f32x2 helpers (register-only; no memory-space asm)
__device__ __forceinline__ unsigned long long f2pack(float lo, float hi) {
    unsigned long long r;
    asm("mov.b64 %0, {%1, %2};" : "=l"(r) : "f"(lo), "f"(hi));
    return r;
}
__device__ __forceinline__ void ffma2(unsigned long long& acc,
                                      unsigned long long a, unsigned long long b) {
    asm("fma.rn.f32x2 %0, %1, %2, %0;" : "+l"(acc) : "l"(a), "l"(b));
}

// ---------------- K1: histogram of dst (4 edges/thread) + prep (block 0) -----
__global__ void k_front(const int* __restrict__ edges, int ne, int n,
                        const float* __restrict__ W, const float* __restrict__ wb,
                        const float* __restrict__ aw, const float* __restrict__ ab) {
    int e0 = (blockIdx.x * blockDim.x + threadIdx.x) * 4;
    if (e0 < ne) {
        if (e0 + 4 <= ne && (ne & 3) == 0) {
            int4 d4 = *(const int4*)&edges[e0];
            if ((unsigned)d4.x < (unsigned)n) atomicAdd(&g_count[d4.x], 1);
            if ((unsigned)d4.y < (unsigned)n) atomicAdd(&g_count[d4.y], 1);
            if ((unsigned)d4.z < (unsigned)n) atomicAdd(&g_count[d4.z], 1);
            if ((unsigned)d4.w < (unsigned)n) atomicAdd(&g_count[d4.w], 1);
        } else {
            for (int e = e0; e < ne && e < e0 + 4; e++) {
                int dst = edges[e];
                if ((unsigned)dst < (unsigned)n) atomicAdd(&g_count[dst], 1);
            }
        }
    }
    if (blockIdx.x == 0 && threadIdx.x < D) {
        int k = threadIdx.x;
        float v1 = 0.f, v2 = 0.f;
#pragma unroll 4
        for (int j = 0; j < D; j++) {
            float w = W[j * D + k];
            v1 += w * aw[j];
            v2 += w * aw[D + j];
        }
        g_v1[k] = v1;
        g_v2[k] = v2;
        if (k == 0) {
            float c = ab[0];
            for (int j = 0; j < D; j++) c += wb[j] * (aw[j] + aw[D + j]);
            g_C = c;
        }
    }
}

// ---------------- K2: node p1/p2 (warp/node) + FULL scan (redundant base) ----
__global__ void __launch_bounds__(SCAN_B) k_midscan(
    const float4* __restrict__ emb4, int n, int nblk) {
    __shared__ int sh[SCAN_B];
    __shared__ int red[SCAN_B / 32];
    int t = threadIdx.x;

    int w = blockIdx.x * 16 + (t >> 5);
    if (w < n) {
        int lane = t & 31;
        float4 e  = emb4[w * 32 + lane];
        float4 a1 = *(const float4*)&g_v1[lane * 4];
        float4 a2 = *(const float4*)&g_v2[lane * 4];
        float d1 = e.x * a1.x + e.y * a1.y + e.z * a1.z + e.w * a1.w;
        float d2 = e.x * a2.x + e.y * a2.y + e.z * a2.z + e.w * a2.w;
#pragma unroll
        for (int o = 16; o; o >>= 1) {
            d1 += __shfl_xor_sync(0xffffffffu, d1, o);
            d2 += __shfl_xor_sync(0xffffffffu, d2, o);
        }
        if (lane == 0) {
            g_p1[w] = d1;
            g_p2[w] = d2;
        }
    }

    if (blockIdx.x >= (unsigned)nblk) return;
    int b = blockIdx.x;
    int tile0 = b * SCAN_B;

    int part = 0;
    for (int idx = t; idx < tile0; idx += SCAN_B) part += g_count[idx];
#pragma unroll
    for (int o = 16; o; o >>= 1) part += __shfl_xor_sync(0xffffffffu, part, o);
    if ((t & 31) == 0) red[t >> 5] = part;
    __syncthreads();
    int base = 0;
#pragma unroll
    for (int q = 0; q < SCAN_B / 32; q++) base += red[q];

    int i = tile0 + t;
    int c = (i < n) ? g_count[i] : 0;
    sh[t] = c;
    __syncthreads();
    for (int d = 1; d < SCAN_B; d <<= 1) {
        int v = (t >= d) ? sh[t - d] : 0;
        __syncthreads();
        sh[t] += v;
        __syncthreads();
    }
    if (i < n) {
        int o = base + sh[t] - c;
        g_off[i]  = o;
        g_woff[i] = o;
    }
    if (b == nblk - 1 && t == SCAN_B - 1) g_off[n] = base + sh[t];
}

// ---------------- K3: attn + scatter edges sorted by dst (4 edges/thread) ----
__device__ __forceinline__ void scat1(int dst, int src, int n) {
    if ((unsigned)dst >= (unsigned)n || (unsigned)src >= (unsigned)n) return;
    float sc = g_p1[dst] + g_p2[src] + g_C;
    sc = sc > 0.f ? sc : 0.2f * sc;
    float attn = __expf(sc);
    int pos = atomicAdd(&g_woff[dst], 1);
    g_spack[pos] = ((unsigned long long)(unsigned)src << 32) | (unsigned long long)__float_as_uint(attn);
}

__global__ void k_scatter(const int* __restrict__ edges, int ne, int n) {
    int e0 = (blockIdx.x * blockDim.x + threadIdx.x) * 4;
    if (e0 >= ne) return;
    if (e0 + 4 <= ne && (ne & 3) == 0) {
        int4 d4 = *(const int4*)&edges[e0];
        int4 s4 = *(const int4*)&edges[ne + e0];
        scat1(d4.x, s4.x, n);
        scat1(d4.y, s4.y, n);
        scat1(d4.z, s4.z, n);
        scat1(d4.w, s4.w, n);
    } else {
        for (int e = e0; e < ne && e < e0 + 4; e++)
            scat1(edges[e], edges[ne + e], n);
    }
}

// ---------------- K4: fused aggregation + [emb|agg] @ T^T + bias + LN --------
// 256 threads = 8 warps; 64 nodes/block. Warp ig owns nodes nb+8*ig..+7.
// Lane = (jg2 = l&15 -> 8 outputs j=8*jg2..+7) x (nh = l>>4 -> 4 of the 8 nodes).
// Thread tile 8j x 4n: per k, 2 LDS.128 (T, half-warp broadcast) + 1 LDS.128
// (X, 2 addrs) feed 16 FFMA2 -> smem-per-MAC halved vs R13 (which was L1-bound
// at 70.5%). X emb-half staged from gmem (L2-resident), agg-half from aggR regs.
// GEMM runs in 8 staged panels of 32 k inside one 33.8 KB smem buffer.
#define TT_STR 132
#define XT_STR 68
#define HS_FLOATS (64 * TT_STR)     // 8448 floats = 33792 B (also holds Tt+Xt)

__global__ void __launch_bounds__(256) k_epi(
    const float4* __restrict__ emb4,
    const float*  __restrict__ T,
    const float*  __restrict__ tb,
    const float*  __restrict__ gamma,
    const float*  __restrict__ beta,
    float*        __restrict__ out, int n)
{
    __shared__ __align__(16) float buf[HS_FLOATS];
    float* Tt = buf;                         // 32 k-rows x TT_STR = 4224 floats
    float* Xt = buf + 32 * TT_STR;           // 32 k-rows x XT_STR = 2176 floats

    int tid = threadIdx.x;
    int l   = tid & 31;
    int ig  = tid >> 5;            // warp -> 8 nodes
    int jg2 = l & 15;              // 8 outputs: j = 8*jg2..+7
    int nh  = l >> 4;              // which 4 nodes of the warp
    int nb  = blockIdx.x * 64;
    const float4* T4 = (const float4*)T;

    // restore g_count = 0 for next call (grid 782*256 >= n)
    {
        int z = blockIdx.x * 256 + tid;
        if (z < n) g_count[z] = 0;
    }

    // ---- phase A: aggregate the warp's 8 nodes into registers ----------------
    // lane l holds agg columns 4l..4l+3 of each node.
    float4 aggR[8];
#pragma unroll
    for (int c = 0; c < 8; c++) {
        int node = nb + 8 * ig + c;
        if (node < n) {
            int beg = g_off[node], end = g_off[node + 1];
            float ax = 0.f, ay = 0.f, az = 0.f, aw = 0.f, den = 0.f;
            for (int base = beg; base < end; base += 32) {
                int m = end - base;
                if (m > 32) m = 32;
                unsigned long long pk = (l < m) ? g_spack[base + l] : 0ULL;
#pragma unroll 4
                for (int t = 0; t < m; t++) {
                    unsigned long long p = __shfl_sync(0xffffffffu, pk, t);
                    float a = __uint_as_float((unsigned)p);
                    int   s = (int)(p >> 32);
                    float4 v = emb4[s * 32 + l];
                    ax += a * v.x; ay += a * v.y; az += a * v.z; aw += a * v.w;
                    den += a;
                }
            }
            float sc1 = 1.0f / (den + 1e-20f);
            aggR[c] = make_float4(ax * sc1, ay * sc1, az * sc1, aw * sc1);
        } else {
            aggR[c] = make_float4(0.f, 0.f, 0.f, 0.f);
        }
    }

    // ---- phase B: GEMM over 8 panels of 32 k --------------------------------
    unsigned long long acc2[16];   // [c*4 + q]: node c (of thread's 4), j-pair q
#pragma unroll
    for (int q = 0; q < 16; q++) acc2[q] = 0ULL;

    for (int p = 0; p < 8; p++) {
        __syncthreads();   // prior panel fully consumed
        // T panel: rows j=0..127, k-slice [p*32, p*32+32), stored transposed
        for (int it = tid; it < 1024; it += 256) {
            int j = it >> 3, k4 = it & 7;
            float4 v = T4[j * 64 + p * 8 + k4];
            int kr = k4 * 4;
            Tt[(kr + 0) * TT_STR + j] = v.x;
            Tt[(kr + 1) * TT_STR + j] = v.y;
            Tt[(kr + 2) * TT_STR + j] = v.z;
            Tt[(kr + 3) * TT_STR + j] = v.w;
        }
        if (p < 4) {
            // X = emb half, staged straight from gmem (L2-resident)
            for (int it = tid; it < 512; it += 256) {
                int i = it >> 3, k4 = it & 7;
                int node = nb + i;
                float4 v = make_float4(0.f, 0.f, 0.f, 0.f);
                if (node < n) v = emb4[node * 32 + p * 8 + k4];
                int kr = k4 * 4;
                Xt[(kr + 0) * XT_STR + i] = v.x;
                Xt[(kr + 1) * XT_STR + i] = v.y;
                Xt[(kr + 2) * XT_STR + i] = v.z;
                Xt[(kr + 3) * XT_STR + i] = v.w;
            }
        } else {
            // X = agg half from registers: lanes [8*(p-4), +8) hold this k-slice
            int lbase = (p - 4) * 8;
            int jl = l - lbase;                  // 0..7 when active
            if (jl >= 0 && jl < 8) {
                int kr = jl * 4;
#pragma unroll
                for (int c = 0; c < 8; c++) {
                    float4 v = aggR[c];
                    int i = 8 * ig + c;
                    Xt[(kr + 0) * XT_STR + i] = v.x;
                    Xt[(kr + 1) * XT_STR + i] = v.y;
                    Xt[(kr + 2) * XT_STR + i] = v.z;
                    Xt[(kr + 3) * XT_STR + i] = v.w;
                }
            }
        }
        __syncthreads();

        const float4* Tt4 = (const float4*)Tt;   // row stride 33 float4
        const float4* Xt4 = (const float4*)Xt;   // row stride 17 float4
#pragma unroll 4
        for (int k = 0; k < 32; k++) {
            float4 t0 = Tt4[k * 33 + 2 * jg2];       // j = 8jg2..+3
            float4 t1 = Tt4[k * 33 + 2 * jg2 + 1];   // j = 8jg2+4..+7
            float4 x  = Xt4[k * 17 + 2 * ig + nh];   // thread's 4 nodes
            unsigned long long tA = f2pack(t0.x, t0.y);
            unsigned long long tB = f2pack(t0.z, t0.w);
            unsigned long long tC = f2pack(t1.x, t1.y);
            unsigned long long tD = f2pack(t1.z, t1.w);
            unsigned long long xA = f2pack(x.x, x.x);
            unsigned long long xB = f2pack(x.y, x.y);
            unsigned long long xC = f2pack(x.z, x.z);
            unsigned long long xD = f2pack(x.w, x.w);
            ffma2(acc2[ 0], tA, xA); ffma2(acc2[ 1], tB, xA);
            ffma2(acc2[ 2], tC, xA); ffma2(acc2[ 3], tD, xA);
            ffma2(acc2[ 4], tA, xB); ffma2(acc2[ 5], tB, xB);
            ffma2(acc2[ 6], tC, xB); ffma2(acc2[ 7], tD, xB);
            ffma2(acc2[ 8], tA, xC); ffma2(acc2[ 9], tB, xC);
            ffma2(acc2[10], tC, xC); ffma2(acc2[11], tD, xC);
            ffma2(acc2[12], tA, xD); ffma2(acc2[13], tB, xD);
            ffma2(acc2[14], tC, xD); ffma2(acc2[15], tD, xD);
        }
    }

    __syncthreads();           // panel reads done; reuse buf as h staging
    float* hs = buf;           // 64 rows x TT_STR
    float bj[8];
#pragma unroll
    for (int r = 0; r < 8; r++) bj[r] = tb[8 * jg2 + r];
#pragma unroll
    for (int c = 0; c < 4; c++) {
        int i = 8 * ig + 4 * nh + c;
#pragma unroll
        for (int q = 0; q < 4; q++) {
            unsigned long long pA = acc2[c * 4 + q];
            hs[i * TT_STR + 8 * jg2 + 2 * q + 0] = __uint_as_float((unsigned)pA) + bj[2 * q + 0];
            hs[i * TT_STR + 8 * jg2 + 2 * q + 1] = __uint_as_float((unsigned)(pA >> 32)) + bj[2 * q + 1];
        }
    }
    __syncthreads();

    // LayerNorm: warp ig handles its 8 nodes
#pragma unroll
    for (int q = 0; q < 8; q++) {
        int i = ig * 8 + q;
        int node = nb + i;
        float4 v = *(const float4*)&hs[i * TT_STR + l * 4];
        float s  = v.x + v.y + v.z + v.w;
        float ss = v.x * v.x + v.y * v.y + v.z * v.z + v.w * v.w;
#pragma unroll
        for (int o = 16; o; o >>= 1) {
            s  += __shfl_xor_sync(0xffffffffu, s,  o);
            ss += __shfl_xor_sync(0xffffffffu, ss, o);
        }
        float mu  = s * (1.0f / 128.0f);
        float var = ss * (1.0f / 128.0f) - mu * mu;
        float rs  = rsqrtf(var + 1e-5f);
        if (node < n) {
            float4 g  = *(const float4*)&gamma[l * 4];
            float4 bb = *(const float4*)&beta[l * 4];
            float4 o4;
            o4.x = (v.x - mu) * rs * g.x + bb.x;
            o4.y = (v.y - mu) * rs * g.y + bb.y;
            o4.z = (v.z - mu) * rs * g.z + bb.z;
            o4.w = (v.w - mu) * rs * g.w + bb.w;
            *(float4*)&out[node * 128 + l * 4] = o4;
        }
    }
}

// ---------------- launch -----------------------------------------------------
extern "C" void kernel_launch(void* const* d_in, const int* in_sizes, int n_in,
                              void* d_out, int out_size) {
    const float* emb   = (const float*)d_in[0];
    const int*   edges = (const int*)d_in[1];       // int64 downcast to int32 by harness
    const float* W     = (const float*)d_in[2];
    const float* wb    = (const float*)d_in[3];
    const float* aw    = (const float*)d_in[4];
    const float* ab    = (const float*)d_in[5];
    const float* T     = (const float*)d_in[6];
    const float* tbias = (const float*)d_in[7];
    const float* gam   = (const float*)d_in[8];
    const float* bet   = (const float*)d_in[9];
    float* out = (float*)d_out;

    int n  = in_sizes[0] / D;   // nodes
    int ne = in_sizes[1] / 2;   // edges
    int nblk  = (n + SCAN_B - 1) / SCAN_B;          // <= 98 for n=50000
    int ne4   = (ne + 3) / 4;
    int nsblk = (n + 15) / 16;                      // node+scan grid (>= nblk)

    k_front  <<<(ne4 + 255) / 256, 256>>>(edges, ne, n, W, wb, aw, ab);
    k_midscan<<<nsblk, SCAN_B>>>((const float4*)emb, n, nblk);
    k_scatter<<<(ne4 + 255) / 256, 256>>>(edges, ne, n);
    k_epi    <<<(n + 63) / 64, 256>>>((const float4*)emb, T, tbias, gam, bet, out, n);
}

// round 16
// speedup vs baseline: 1.1868x; 1.1868x over previous
#include <cuda_runtime.h>

#define NN      50000
#define NEMAX   800000
#define D       128
#define SCAN_B  512

// ---------------- scratch (static device globals; no runtime alloc) ----------
// g_count invariant: zero at entry of every kernel_launch call.
// (a) zero-init at module load; (b) k_epi re-zeroes it each call.
__device__ __align__(16) float g_v1[D];
__device__ __align__(16) float g_v2[D];
__device__ float g_C;
__device__ float g_p1[NN];
__device__ float g_p2[NN];
__device__ int   g_count[NN];
__device__ int   g_off[NN + 1];
__device__ int   g_woff[NN];
__device__ unsigned long long g_spack[NEMAX];      // {src:hi32, attn:lo32}

// packed f32x2 helpers (register-only; no memory-space asm)
__device__ __forceinline__ unsigned long long f2pack(float lo, float hi) {
    unsigned long long r;
    asm("mov.b64 %0, {%1, %2};" : "=l"(r) : "f"(lo), "f"(hi));
    return r;
}
__device__ __forceinline__ void ffma2(unsigned long long& acc,
                                      unsigned long long a, unsigned long long b) {
    asm("fma.rn.f32x2 %0, %1, %2, %0;" : "+l"(acc) : "l"(a), "l"(b));
}

// ---------------- K1: histogram of dst (4 edges/thread) + prep (block 0) -----
__global__ void k_front(const int* __restrict__ edges, int ne, int n,
                        const float* __restrict__ W, const float* __restrict__ wb,
                        const float* __restrict__ aw, const float* __restrict__ ab) {
    int e0 = (blockIdx.x * blockDim.x + threadIdx.x) * 4;
    if (e0 < ne) {
        if (e0 + 4 <= ne && (ne & 3) == 0) {
            int4 d4 = *(const int4*)&edges[e0];
            if ((unsigned)d4.x < (unsigned)n) atomicAdd(&g_count[d4.x], 1);
            if ((unsigned)d4.y < (unsigned)n) atomicAdd(&g_count[d4.y], 1);
            if ((unsigned)d4.z < (unsigned)n) atomicAdd(&g_count[d4.z], 1);
            if ((unsigned)d4.w < (unsigned)n) atomicAdd(&g_count[d4.w], 1);
        } else {
            for (int e = e0; e < ne && e < e0 + 4; e++) {
                int dst = edges[e];
                if ((unsigned)dst < (unsigned)n) atomicAdd(&g_count[dst], 1);
            }
        }
    }
    if (blockIdx.x == 0 && threadIdx.x < D) {
        int k = threadIdx.x;
        float v1 = 0.f, v2 = 0.f;
#pragma unroll 4
        for (int j = 0; j < D; j++) {
            float w = W[j * D + k];
            v1 += w * aw[j];
            v2 += w * aw[D + j];
        }
        g_v1[k] = v1;
        g_v2[k] = v2;
        if (k == 0) {
            float c = ab[0];
            for (int j = 0; j < D; j++) c += wb[j] * (aw[j] + aw[D + j]);
            g_C = c;
        }
    }
}

// ---------------- K2: node p1/p2 (warp/node) + FULL scan (redundant base) ----
__global__ void __launch_bounds__(SCAN_B) k_midscan(
    const float4* __restrict__ emb4, int n, int nblk) {
    __shared__ int sh[SCAN_B];
    __shared__ int red[SCAN_B / 32];
    int t = threadIdx.x;

    int w = blockIdx.x * 16 + (t >> 5);
    if (w < n) {
        int lane = t & 31;
        float4 e  = emb4[w * 32 + lane];
        float4 a1 = *(const float4*)&g_v1[lane * 4];
        float4 a2 = *(const float4*)&g_v2[lane * 4];
        float d1 = e.x * a1.x + e.y * a1.y + e.z * a1.z + e.w * a1.w;
        float d2 = e.x * a2.x + e.y * a2.y + e.z * a2.z + e.w * a2.w;
#pragma unroll
        for (int o = 16; o; o >>= 1) {
            d1 += __shfl_xor_sync(0xffffffffu, d1, o);
            d2 += __shfl_xor_sync(0xffffffffu, d2, o);
        }
        if (lane == 0) {
            g_p1[w] = d1;
            g_p2[w] = d2;
        }
    }

    if (blockIdx.x >= (unsigned)nblk) return;
    int b = blockIdx.x;
    int tile0 = b * SCAN_B;

    int part = 0;
    for (int idx = t; idx < tile0; idx += SCAN_B) part += g_count[idx];
#pragma unroll
    for (int o = 16; o; o >>= 1) part += __shfl_xor_sync(0xffffffffu, part, o);
    if ((t & 31) == 0) red[t >> 5] = part;
    __syncthreads();
    int base = 0;
#pragma unroll
    for (int q = 0; q < SCAN_B / 32; q++) base += red[q];

    int i = tile0 + t;
    int c = (i < n) ? g_count[i] : 0;
    sh[t] = c;
    __syncthreads();
    for (int d = 1; d < SCAN_B; d <<= 1) {
        int v = (t >= d) ? sh[t - d] : 0;
        __syncthreads();
        sh[t] += v;
        __syncthreads();
    }
    if (i < n) {
        int o = base + sh[t] - c;
        g_off[i]  = o;
        g_woff[i] = o;
    }
    if (b == nblk - 1 && t == SCAN_B - 1) g_off[n] = base + sh[t];
}

// ---------------- K3: attn + scatter edges sorted by dst (4 edges/thread) ----
__device__ __forceinline__ void scat1(int dst, int src, int n) {
    if ((unsigned)dst >= (unsigned)n || (unsigned)src >= (unsigned)n) return;
    float sc = g_p1[dst] + g_p2[src] + g_C;
    sc = sc > 0.f ? sc : 0.2f * sc;
    float attn = __expf(sc);
    int pos = atomicAdd(&g_woff[dst], 1);
    g_spack[pos] = ((unsigned long long)(unsigned)src << 32) | (unsigned long long)__float_as_uint(attn);
}

__global__ void k_scatter(const int* __restrict__ edges, int ne, int n) {
    int e0 = (blockIdx.x * blockDim.x + threadIdx.x) * 4;
    if (e0 >= ne) return;
    if (e0 + 4 <= ne && (ne & 3) == 0) {
        int4 d4 = *(const int4*)&edges[e0];
        int4 s4 = *(const int4*)&edges[ne + e0];
        scat1(d4.x, s4.x, n);
        scat1(d4.y, s4.y, n);
        scat1(d4.z, s4.z, n);
        scat1(d4.w, s4.w, n);
    } else {
        for (int e = e0; e < ne && e < e0 + 4; e++)
            scat1(edges[e], edges[ne + e], n);
    }
}

// ---------------- K4: fused aggregation + [emb|agg] @ T^T + bias + LN --------
// R13 structure (best): 256 threads = 32 lanes (jg) x 8 warps (ig); 32 nodes/
// block; warp owns 4 nodes. Changes vs R13: embR dropped (emb X-half staged
// straight from L2-resident gmem) and __launch_bounds__(256,4) to cap regs at
// 64 -> 4 blocks/SM = 32 warps (R13: 24). Phase A is latency-bound (L2=8.8%,
// DRAM=1.8% in profiles) -> +33% resident warps attacks the true bottleneck.
#define TT_STR 132
#define XT_STR 36

__global__ void __launch_bounds__(256, 4) k_epi(
    const float4* __restrict__ emb4,
    const float*  __restrict__ T,
    const float*  __restrict__ tb,
    const float*  __restrict__ gamma,
    const float*  __restrict__ beta,
    float*        __restrict__ out, int n)
{
    __shared__ __align__(16) float Tt[64 * TT_STR];   // 33792 B
    __shared__ __align__(16) float Xt[64 * XT_STR];   //  9216 B

    int tid = threadIdx.x;
    int jg  = tid & 31;        // lane
    int ig  = tid >> 5;        // warp -> node group (i = 4*ig + c)
    int nb  = blockIdx.x * 32;
    const float4* T4 = (const float4*)T;

    // restore g_count = 0 for the next kernel_launch call (grid*256 >= n)
    {
        int z = blockIdx.x * 256 + tid;
        if (z < n) g_count[z] = 0;
    }

    // ---- phase A: per-warp neighbor aggregation into registers --------------
    float4 aggR[4];
#pragma unroll
    for (int c = 0; c < 4; c++) {
        int node = nb + 4 * ig + c;
        if (node < n) {
            int beg = g_off[node], end = g_off[node + 1];
            float ax = 0.f, ay = 0.f, az = 0.f, aw = 0.f, den = 0.f;
            for (int base = beg; base < end; base += 32) {
                int m = end - base;
                if (m > 32) m = 32;
                unsigned long long pk = (jg < m) ? g_spack[base + jg] : 0ULL;
#pragma unroll 4
                for (int t = 0; t < m; t++) {
                    unsigned long long p = __shfl_sync(0xffffffffu, pk, t);
                    float a = __uint_as_float((unsigned)p);
                    int   s = (int)(p >> 32);
                    float4 v = emb4[s * 32 + jg];
                    ax += a * v.x; ay += a * v.y; az += a * v.z; aw += a * v.w;
                    den += a;
                }
            }
            float sc1 = 1.0f / (den + 1e-20f);
            aggR[c] = make_float4(ax * sc1, ay * sc1, az * sc1, aw * sc1);
        } else {
            aggR[c] = make_float4(0.f, 0.f, 0.f, 0.f);
        }
    }

    // ---- phase B: GEMM over 4 panels of 64 k --------------------------------
    unsigned long long acc2[8];
#pragma unroll
    for (int q = 0; q < 8; q++) acc2[q] = 0ULL;

    for (int p = 0; p < 4; p++) {
        __syncthreads();   // prior panels fully consumed
        // T panel: rows j = 0..127, k-slice [p*64, p*64+64), stored transposed
        for (int it = tid; it < 2048; it += 256) {
            int j = it >> 4, k4 = it & 15;
            float4 v = T4[j * 64 + p * 16 + k4];
            int kr = k4 * 4;
            Tt[(kr + 0) * TT_STR + j] = v.x;
            Tt[(kr + 1) * TT_STR + j] = v.y;
            Tt[(kr + 2) * TT_STR + j] = v.z;
            Tt[(kr + 3) * TT_STR + j] = v.w;
        }
        if (p < 2) {
            // X = emb half, staged straight from gmem (L2-resident)
            for (int it = tid; it < 512; it += 256) {
                int i = it >> 4, k4 = it & 15;
                int node = nb + i;
                float4 v = make_float4(0.f, 0.f, 0.f, 0.f);
                if (node < n) v = emb4[node * 32 + p * 16 + k4];
                int kr = k4 * 4;
                Xt[(kr + 0) * XT_STR + i] = v.x;
                Xt[(kr + 1) * XT_STR + i] = v.y;
                Xt[(kr + 2) * XT_STR + i] = v.z;
                Xt[(kr + 3) * XT_STR + i] = v.w;
            }
        } else {
            // X = agg half from registers: lanes [16*(p&1), +16) hold this slice
            int base = (p & 1) * 16;
            int jl = jg - base;                 // 0..15 when active
            if (jl >= 0 && jl < 16) {
                int kr = jl * 4;
#pragma unroll
                for (int c = 0; c < 4; c++) {
                    float4 v = aggR[c];
                    int i = 4 * ig + c;
                    Xt[(kr + 0) * XT_STR + i] = v.x;
                    Xt[(kr + 1) * XT_STR + i] = v.y;
                    Xt[(kr + 2) * XT_STR + i] = v.z;
                    Xt[(kr + 3) * XT_STR + i] = v.w;
                }
            }
        }
        __syncthreads();

        const float4* Tt4 = (const float4*)Tt;   // row stride 33 float4
        const float4* Xt4 = (const float4*)Xt;   // row stride  9 float4
#pragma unroll 4
        for (int k = 0; k < 64; k++) {
            float4 t = Tt4[k * 33 + jg];   // T[4jg+0..3][k]
            float4 x = Xt4[k * 9 + ig];    // X[4ig+0..3][k]  (broadcast)
            unsigned long long tA = f2pack(t.x, t.y);
            unsigned long long tB = f2pack(t.z, t.w);
            unsigned long long xA = f2pack(x.x, x.x);
            unsigned long long xB = f2pack(x.y, x.y);
            unsigned long long xC = f2pack(x.z, x.z);
            unsigned long long xD = f2pack(x.w, x.w);
            ffma2(acc2[0], tA, xA); ffma2(acc2[1], tB, xA);
            ffma2(acc2[2], tA, xB); ffma2(acc2[3], tB, xB);
            ffma2(acc2[4], tA, xC); ffma2(acc2[5], tB, xC);
            ffma2(acc2[6], tA, xD); ffma2(acc2[7], tB, xD);
        }
    }

    __syncthreads();           // Tt reads done; reuse as h staging
    float* hs = Tt;            // 32 rows x TT_STR
    float b0 = tb[4 * jg + 0], b1 = tb[4 * jg + 1], b2 = tb[4 * jg + 2], b3 = tb[4 * jg + 3];
#pragma unroll
    for (int c = 0; c < 4; c++) {
        int i = 4 * ig + c;
        unsigned long long pA = acc2[c * 2 + 0], pB = acc2[c * 2 + 1];
        hs[i * TT_STR + 4 * jg + 0] = __uint_as_float((unsigned)pA) + b0;
        hs[i * TT_STR + 4 * jg + 1] = __uint_as_float((unsigned)(pA >> 32)) + b1;
        hs[i * TT_STR + 4 * jg + 2] = __uint_as_float((unsigned)pB) + b2;
        hs[i * TT_STR + 4 * jg + 3] = __uint_as_float((unsigned)(pB >> 32)) + b3;
    }
    __syncthreads();

    // LayerNorm: warp ig handles nodes 4*ig..4*ig+3
    int lane = jg;
#pragma unroll
    for (int q = 0; q < 4; q++) {
        int i = ig * 4 + q;
        int node = nb + i;
        float4 v = *(const float4*)&hs[i * TT_STR + lane * 4];
        float s  = v.x + v.y + v.z + v.w;
        float ss = v.x * v.x + v.y * v.y + v.z * v.z + v.w * v.w;
#pragma unroll
        for (int o = 16; o; o >>= 1) {
            s  += __shfl_xor_sync(0xffffffffu, s,  o);
            ss += __shfl_xor_sync(0xffffffffu, ss, o);
        }
        float mu  = s * (1.0f / 128.0f);
        float var = ss * (1.0f / 128.0f) - mu * mu;
        float rs  = rsqrtf(var + 1e-5f);
        if (node < n) {
            float4 g  = *(const float4*)&gamma[lane * 4];
            float4 bb = *(const float4*)&beta[lane * 4];
            float4 o4;
            o4.x = (v.x - mu) * rs * g.x + bb.x;
            o4.y = (v.y - mu) * rs * g.y + bb.y;
            o4.z = (v.z - mu) * rs * g.z + bb.z;
            o4.w = (v.w - mu) * rs * g.w + bb.w;
            *(float4*)&out[node * 128 + lane * 4] = o4;
        }
    }
}

// ---------------- launch -----------------------------------------------------
extern "C" void kernel_launch(void* const* d_in, const int* in_sizes, int n_in,
                              void* d_out, int out_size) {
    const float* emb   = (const float*)d_in[0];
    const int*   edges = (const int*)d_in[1];       // int64 downcast to int32 by harness
    const float* W     = (const float*)d_in[2];
    const float* wb    = (const float*)d_in[3];
    const float* aw    = (const float*)d_in[4];
    const float* ab    = (const float*)d_in[5];
    const float* T     = (const float*)d_in[6];
    const float* tbias = (const float*)d_in[7];
    const float* gam   = (const float*)d_in[8];
    const float* bet   = (const float*)d_in[9];
    float* out = (float*)d_out;

    int n  = in_sizes[0] / D;   // nodes
    int ne = in_sizes[1] / 2;   // edges
    int nblk  = (n + SCAN_B - 1) / SCAN_B;          // <= 98 for n=50000
    int ne4   = (ne + 3) / 4;
    int nsblk = (n + 15) / 16;                      // node+scan grid (>= nblk)

    k_front  <<<(ne4 + 255) / 256, 256>>>(edges, ne, n, W, wb, aw, ab);
    k_midscan<<<nsblk, SCAN_B>>>((const float4*)emb, n, nblk);
    k_scatter<<<(ne4 + 255) / 256, 256>>>(edges, ne, n);
    k_epi    <<<(n + 31) / 32, 256>>>((const float4*)emb, T, tbias, gam, bet, out, n);
}

// round 17
// speedup vs baseline: 1.1927x; 1.0050x over previous
#include <cuda_runtime.h>

#define NN      50000
#define NEMAX   800000
#define D       128
#define SCAN_B  512

// ---------------- scratch (static device globals; no runtime alloc) ----------
// g_count invariant: zero at entry of every kernel_launch call.
// (a) zero-init at module load; (b) k_epi re-zeroes it each call.
__device__ __align__(16) float g_v1[D];
__device__ __align__(16) float g_v2[D];
__device__ float g_C;
__device__ float g_p1[NN];
__device__ float g_p2[NN];
__device__ int   g_count[NN];
__device__ int   g_off[NN + 1];
__device__ int   g_woff[NN];
__device__ unsigned long long g_spack[NEMAX];      // {src:hi32, attn:lo32}

// packed f32x2 helpers (register-only; no memory-space asm)
__device__ __forceinline__ unsigned long long f2pack(float lo, float hi) {
    unsigned long long r;
    asm("mov.b64 %0, {%1, %2};" : "=l"(r) : "f"(lo), "f"(hi));
    return r;
}
__device__ __forceinline__ void ffma2(unsigned long long& acc,
                                      unsigned long long a, unsigned long long b) {
    asm("fma.rn.f32x2 %0, %1, %2, %0;" : "+l"(acc) : "l"(a), "l"(b));
}

// ---------------- K1: histogram of dst (4 edges/thread) + prep (block 0) -----
__global__ void k_front(const int* __restrict__ edges, int ne, int n,
                        const float* __restrict__ W, const float* __restrict__ wb,
                        const float* __restrict__ aw, const float* __restrict__ ab) {
    int e0 = (blockIdx.x * blockDim.x + threadIdx.x) * 4;
    if (e0 < ne) {
        if (e0 + 4 <= ne && (ne & 3) == 0) {
            int4 d4 = *(const int4*)&edges[e0];
            if ((unsigned)d4.x < (unsigned)n) atomicAdd(&g_count[d4.x], 1);
            if ((unsigned)d4.y < (unsigned)n) atomicAdd(&g_count[d4.y], 1);
            if ((unsigned)d4.z < (unsigned)n) atomicAdd(&g_count[d4.z], 1);
            if ((unsigned)d4.w < (unsigned)n) atomicAdd(&g_count[d4.w], 1);
        } else {
            for (int e = e0; e < ne && e < e0 + 4; e++) {
                int dst = edges[e];
                if ((unsigned)dst < (unsigned)n) atomicAdd(&g_count[dst], 1);
            }
        }
    }
    if (blockIdx.x == 0 && threadIdx.x < D) {
        int k = threadIdx.x;
        float v1 = 0.f, v2 = 0.f;
#pragma unroll 4
        for (int j = 0; j < D; j++) {
            float w = W[j * D + k];
            v1 += w * aw[j];
            v2 += w * aw[D + j];
        }
        g_v1[k] = v1;
        g_v2[k] = v2;
        if (k == 0) {
            float c = ab[0];
            for (int j = 0; j < D; j++) c += wb[j] * (aw[j] + aw[D + j]);
            g_C = c;
        }
    }
}

// ---------------- K2: node p1/p2 (warp/node) + FULL scan (redundant base) ----
__global__ void __launch_bounds__(SCAN_B) k_midscan(
    const float4* __restrict__ emb4, int n, int nblk) {
    __shared__ int sh[SCAN_B];
    __shared__ int red[SCAN_B / 32];
    int t = threadIdx.x;

    int w = blockIdx.x * 16 + (t >> 5);
    if (w < n) {
        int lane = t & 31;
        float4 e  = emb4[w * 32 + lane];
        float4 a1 = *(const float4*)&g_v1[lane * 4];
        float4 a2 = *(const float4*)&g_v2[lane * 4];
        float d1 = e.x * a1.x + e.y * a1.y + e.z * a1.z + e.w * a1.w;
        float d2 = e.x * a2.x + e.y * a2.y + e.z * a2.z + e.w * a2.w;
#pragma unroll
        for (int o = 16; o; o >>= 1) {
            d1 += __shfl_xor_sync(0xffffffffu, d1, o);
            d2 += __shfl_xor_sync(0xffffffffu, d2, o);
        }
        if (lane == 0) {
            g_p1[w] = d1;
            g_p2[w] = d2;
        }
    }

    if (blockIdx.x >= (unsigned)nblk) return;
    int b = blockIdx.x;
    int tile0 = b * SCAN_B;

    int part = 0;
    for (int idx = t; idx < tile0; idx += SCAN_B) part += g_count[idx];
#pragma unroll
    for (int o = 16; o; o >>= 1) part += __shfl_xor_sync(0xffffffffu, part, o);
    if ((t & 31) == 0) red[t >> 5] = part;
    __syncthreads();
    int base = 0;
#pragma unroll
    for (int q = 0; q < SCAN_B / 32; q++) base += red[q];

    int i = tile0 + t;
    int c = (i < n) ? g_count[i] : 0;
    sh[t] = c;
    __syncthreads();
    for (int d = 1; d < SCAN_B; d <<= 1) {
        int v = (t >= d) ? sh[t - d] : 0;
        __syncthreads();
        sh[t] += v;
        __syncthreads();
    }
    if (i < n) {
        int o = base + sh[t] - c;
        g_off[i]  = o;
        g_woff[i] = o;
    }
    if (b == nblk - 1 && t == SCAN_B - 1) g_off[n] = base + sh[t];
}

// ---------------- K3: attn + scatter edges sorted by dst (4 edges/thread) ----
__device__ __forceinline__ void scat1(int dst, int src, int n) {
    if ((unsigned)dst >= (unsigned)n || (unsigned)src >= (unsigned)n) return;
    float sc = g_p1[dst] + g_p2[src] + g_C;
    sc = sc > 0.f ? sc : 0.2f * sc;
    float attn = __expf(sc);
    int pos = atomicAdd(&g_woff[dst], 1);
    g_spack[pos] = ((unsigned long long)(unsigned)src << 32) | (unsigned long long)__float_as_uint(attn);
}

__global__ void k_scatter(const int* __restrict__ edges, int ne, int n) {
    int e0 = (blockIdx.x * blockDim.x + threadIdx.x) * 4;
    if (e0 >= ne) return;
    if (e0 + 4 <= ne && (ne & 3) == 0) {
        int4 d4 = *(const int4*)&edges[e0];
        int4 s4 = *(const int4*)&edges[ne + e0];
        scat1(d4.x, s4.x, n);
        scat1(d4.y, s4.y, n);
        scat1(d4.z, s4.z, n);
        scat1(d4.w, s4.w, n);
    } else {
        for (int e = e0; e < ne && e < e0 + 4; e++)
            scat1(edges[e], edges[ne + e], n);
    }
}

// ---------------- K4: fused aggregation + [emb|agg] @ T^T + bias + LN --------
// R16 base (WIN: occ 4 blocks/SM, regs 64) with phase-B remapped to kill the
// smem-wavefront bottleneck (R16 profile: L1=80.3%, fma=30.7%).
// Phase B now partitions j ACROSS warps: warp ig computes j in [16ig,16ig+16)
// for ALL 32 nodes. Lane = (jg4=l&3 -> 4 j's) x (ng=l>>2 -> 4 nodes).
// Per warp-k: T read = 4 consecutive float4 (64B, broadcast) = 1 wf;
// X read = 8 consecutive float4 (128B, broadcast) = 1 wf; feeding 8 FFMA2.
// Block-k wavefronts: 40 (R16) -> 16.
#define TT_STR 132
#define XT_STR 36

__global__ void __launch_bounds__(256, 4) k_epi(
    const float4* __restrict__ emb4,
    const float*  __restrict__ T,
    const float*  __restrict__ tb,
    const float*  __restrict__ gamma,
    const float*  __restrict__ beta,
    float*        __restrict__ out, int n)
{
    __shared__ __align__(16) float Tt[64 * TT_STR];   // 33792 B
    __shared__ __align__(16) float Xt[64 * XT_STR];   //  9216 B

    int tid = threadIdx.x;
    int jg  = tid & 31;        // lane
    int ig  = tid >> 5;        // warp
    int nb  = blockIdx.x * 32;
    const float4* T4 = (const float4*)T;

    // restore g_count = 0 for the next kernel_launch call (grid*256 >= n)
    {
        int z = blockIdx.x * 256 + tid;
        if (z < n) g_count[z] = 0;
    }

    // ---- phase A: per-warp neighbor aggregation into registers --------------
    // warp ig owns nodes nb+4*ig..+3; lane l holds agg columns 4l..4l+3.
    float4 aggR[4];
#pragma unroll
    for (int c = 0; c < 4; c++) {
        int node = nb + 4 * ig + c;
        if (node < n) {
            int beg = g_off[node], end = g_off[node + 1];
            float ax = 0.f, ay = 0.f, az = 0.f, aw = 0.f, den = 0.f;
            for (int base = beg; base < end; base += 32) {
                int m = end - base;
                if (m > 32) m = 32;
                unsigned long long pk = (jg < m) ? g_spack[base + jg] : 0ULL;
#pragma unroll 4
                for (int t = 0; t < m; t++) {
                    unsigned long long p = __shfl_sync(0xffffffffu, pk, t);
                    float a = __uint_as_float((unsigned)p);
                    int   s = (int)(p >> 32);
                    float4 v = emb4[s * 32 + jg];
                    ax += a * v.x; ay += a * v.y; az += a * v.z; aw += a * v.w;
                    den += a;
                }
            }
            float sc1 = 1.0f / (den + 1e-20f);
            aggR[c] = make_float4(ax * sc1, ay * sc1, az * sc1, aw * sc1);
        } else {
            aggR[c] = make_float4(0.f, 0.f, 0.f, 0.f);
        }
    }

    // ---- phase B: GEMM over 4 panels of 64 k --------------------------------
    int jg4 = jg & 3;          // which float4 of the warp's 16-j slice
    int ng  = jg >> 2;         // which 4-node group (of 8)
    unsigned long long acc2[8];
#pragma unroll
    for (int q = 0; q < 8; q++) acc2[q] = 0ULL;

    for (int p = 0; p < 4; p++) {
        __syncthreads();   // prior panels fully consumed
        // T panel: rows j = 0..127, k-slice [p*64, p*64+64), stored transposed
        for (int it = tid; it < 2048; it += 256) {
            int j = it >> 4, k4 = it & 15;
            float4 v = T4[j * 64 + p * 16 + k4];
            int kr = k4 * 4;
            Tt[(kr + 0) * TT_STR + j] = v.x;
            Tt[(kr + 1) * TT_STR + j] = v.y;
            Tt[(kr + 2) * TT_STR + j] = v.z;
            Tt[(kr + 3) * TT_STR + j] = v.w;
        }
        if (p < 2) {
            // X = emb half, staged straight from gmem (L2-resident)
            for (int it = tid; it < 512; it += 256) {
                int i = it >> 4, k4 = it & 15;
                int node = nb + i;
                float4 v = make_float4(0.f, 0.f, 0.f, 0.f);
                if (node < n) v = emb4[node * 32 + p * 16 + k4];
                int kr = k4 * 4;
                Xt[(kr + 0) * XT_STR + i] = v.x;
                Xt[(kr + 1) * XT_STR + i] = v.y;
                Xt[(kr + 2) * XT_STR + i] = v.z;
                Xt[(kr + 3) * XT_STR + i] = v.w;
            }
        } else {
            // X = agg half from registers: lanes [16*(p&1), +16) hold this slice
            int base = (p & 1) * 16;
            int jl = jg - base;                 // 0..15 when active
            if (jl >= 0 && jl < 16) {
                int kr = jl * 4;
#pragma unroll
                for (int c = 0; c < 4; c++) {
                    float4 v = aggR[c];
                    int i = 4 * ig + c;
                    Xt[(kr + 0) * XT_STR + i] = v.x;
                    Xt[(kr + 1) * XT_STR + i] = v.y;
                    Xt[(kr + 2) * XT_STR + i] = v.z;
                    Xt[(kr + 3) * XT_STR + i] = v.w;
                }
            }
        }
        __syncthreads();

        const float4* Tt4 = (const float4*)Tt;   // row stride 33 float4
        const float4* Xt4 = (const float4*)Xt;   // row stride  9 float4
#pragma unroll 4
        for (int k = 0; k < 64; k++) {
            float4 t = Tt4[k * 33 + 4 * ig + jg4];  // T[16ig+4jg4 .. +3][k], 64B/warp
            float4 x = Xt4[k * 9 + ng];             // X[4ng .. 4ng+3][k], 128B/warp
            unsigned long long tA = f2pack(t.x, t.y);
            unsigned long long tB = f2pack(t.z, t.w);
            unsigned long long xA = f2pack(x.x, x.x);
            unsigned long long xB = f2pack(x.y, x.y);
            unsigned long long xC = f2pack(x.z, x.z);
            unsigned long long xD = f2pack(x.w, x.w);
            ffma2(acc2[0], tA, xA); ffma2(acc2[1], tB, xA);
            ffma2(acc2[2], tA, xB); ffma2(acc2[3], tB, xB);
            ffma2(acc2[4], tA, xC); ffma2(acc2[5], tB, xC);
            ffma2(acc2[6], tA, xD); ffma2(acc2[7], tB, xD);
        }
    }

    __syncthreads();           // Tt reads done; reuse as h staging
    float* hs = Tt;            // 32 rows x TT_STR
    int jb = 16 * ig + 4 * jg4;            // this thread's j base
    float b0 = tb[jb + 0], b1 = tb[jb + 1], b2 = tb[jb + 2], b3 = tb[jb + 3];
#pragma unroll
    for (int c = 0; c < 4; c++) {
        int i = 4 * ng + c;                // node row
        unsigned long long pA = acc2[c * 2 + 0], pB = acc2[c * 2 + 1];
        hs[i * TT_STR + jb + 0] = __uint_as_float((unsigned)pA) + b0;
        hs[i * TT_STR + jb + 1] = __uint_as_float((unsigned)(pA >> 32)) + b1;
        hs[i * TT_STR + jb + 2] = __uint_as_float((unsigned)pB) + b2;
        hs[i * TT_STR + jb + 3] = __uint_as_float((unsigned)(pB >> 32)) + b3;
    }
    __syncthreads();

    // LayerNorm: warp ig handles nodes 4*ig..4*ig+3
    int lane = jg;
#pragma unroll
    for (int q = 0; q < 4; q++) {
        int i = ig * 4 + q;
        int node = nb + i;
        float4 v = *(const float4*)&hs[i * TT_STR + lane * 4];
        float s  = v.x + v.y + v.z + v.w;
        float ss = v.x * v.x + v.y * v.y + v.z * v.z + v.w * v.w;
#pragma unroll
        for (int o = 16; o; o >>= 1) {
            s  += __shfl_xor_sync(0xffffffffu, s,  o);
            ss += __shfl_xor_sync(0xffffffffu, ss, o);
        }
        float mu  = s * (1.0f / 128.0f);
        float var = ss * (1.0f / 128.0f) - mu * mu;
        float rs  = rsqrtf(var + 1e-5f);
        if (node < n) {
            float4 g  = *(const float4*)&gamma[lane * 4];
            float4 bb = *(const float4*)&beta[lane * 4];
            float4 o4;
            o4.x = (v.x - mu) * rs * g.x + bb.x;
            o4.y = (v.y - mu) * rs * g.y + bb.y;
            o4.z = (v.z - mu) * rs * g.z + bb.z;
            o4.w = (v.w - mu) * rs * g.w + bb.w;
            *(float4*)&out[node * 128 + lane * 4] = o4;
        }
    }
}

// ---------------- launch -----------------------------------------------------
extern "C" void kernel_launch(void* const* d_in, const int* in_sizes, int n_in,
                              void* d_out, int out_size) {
    const float* emb   = (const float*)d_in[0];
    const int*   edges = (const int*)d_in[1];       // int64 downcast to int32 by harness
    const float* W     = (const float*)d_in[2];
    const float* wb    = (const float*)d_in[3];
    const float* aw    = (const float*)d_in[4];
    const float* ab    = (const float*)d_in[5];
    const float* T     = (const float*)d_in[6];
    const float* tbias = (const float*)d_in[7];
    const float* gam   = (const float*)d_in[8];
    const float* bet   = (const float*)d_in[9];
    float* out = (float*)d_out;

    int n  = in_sizes[0] / D;   // nodes
    int ne = in_sizes[1] / 2;   // edges
    int nblk  = (n + SCAN_B - 1) / SCAN_B;          // <= 98 for n=50000
    int ne4   = (ne + 3) / 4;
    int nsblk = (n + 15) / 16;                      // node+scan grid (>= nblk)

    k_front  <<<(ne4 + 255) / 256, 256>>>(edges, ne, n, W, wb, aw, ab);
    k_midscan<<<nsblk, SCAN_B>>>((const float4*)emb, n, nblk);
    k_scatter<<<(ne4 + 255) / 256, 256>>>(edges, ne, n);
    k_epi    <<<(n + 31) / 32, 256>>>((const float4*)emb, T, tbias, gam, bet, out, n);
}